// round 13
// baseline (speedup 1.0000x reference)
#include <cuda_runtime.h>
#include <cuda_fp16.h>
#include <math.h>

#define DMAX   256
#define NMAX   50000
#define TMAX   400000
#define RMAX   1000
#define DEPMAX 2
#define SCAN_CHUNK 2048   // elements per scan block (256 thr * 8)

// ---------------- static device scratch (no allocation allowed) ----------------
__device__ __align__(16) __half g_xA[(size_t)NMAX * DMAX];    // 25.6 MB
__device__ __align__(16) __half g_xB[(size_t)NMAX * DMAX];    // 25.6 MB
__device__ __align__(16) __half g_nrel[(size_t)RMAX * DMAX];  // 512 KB
__device__ float g_attrel[DEPMAX * RMAX];
__device__ float g_w[(size_t)DEPMAX * TMAX];   // per-edge softmax weights per layer
__device__ int   g_counts[NMAX + 1];
__device__ int   g_rowptr[NMAX + 1];
__device__ int   g_cursor[NMAX];
__device__ int   g_bsum[64];
__device__ int   g_srcp[TMAX];
__device__ int   g_reli[TMAX];      // relation index per CSR edge, -1 if zero tri_rel
__device__ int   g_relcode[TMAX];   // signed code per CSR edge: 0 or +-(rel+1)
__device__ int   g_tricode[TMAX];   // per-triple code before CSR permutation
__device__ int   g_flag64;          // 1 if index arrays are int64, 0 if int32

// ---------------- helpers ----------------
__device__ __forceinline__ long long ld_idx(const void* p, long long i) {
    return g_flag64 ? ((const long long*)p)[i] : (long long)((const int*)p)[i];
}

__device__ __forceinline__ float blockReduce256(float v, float* sm) {
    #pragma unroll
    for (int off = 16; off; off >>= 1) v += __shfl_xor_sync(0xffffffffu, v, off);
    int w = threadIdx.x >> 5;
    if ((threadIdx.x & 31) == 0) sm[w] = v;
    __syncthreads();
    if (threadIdx.x < 32) {
        float r = (threadIdx.x < 8) ? sm[threadIdx.x] : 0.0f;
        #pragma unroll
        for (int off = 4; off; off >>= 1) r += __shfl_xor_sync(0xffffffffu, r, off);
        if (threadIdx.x == 0) sm[0] = r;
    }
    __syncthreads();
    float res = sm[0];
    __syncthreads();
    return res;
}

// dot of 8 fp16 pairs held as raw uint4 (convert on the fly, f32 fma accumulate)
__device__ __forceinline__ float dot8h(const uint4& xr, const uint4& vr) {
    const __half2* hx = (const __half2*)&xr;
    const __half2* hv = (const __half2*)&vr;
    float p = 0.0f;
    #pragma unroll
    for (int i = 0; i < 4; i++) {
        float2 a = __half22float2(hx[i]);
        float2 b = __half22float2(hv[i]);
        p = fmaf(a.x, b.x, p);
        p = fmaf(a.y, b.y, p);
    }
    return p;
}

// acc += w * (x - t2 * v), operands raw fp16
__device__ __forceinline__ void axpy8h(float acc[8], float w, float t2,
                                       const uint4& xr, const uint4& vr) {
    const __half2* hx = (const __half2*)&xr;
    const __half2* hv = (const __half2*)&vr;
    #pragma unroll
    for (int i = 0; i < 4; i++) {
        float2 a = __half22float2(hx[i]);
        float2 b = __half22float2(hv[i]);
        acc[2 * i]     += w * (a.x - t2 * b.x);
        acc[2 * i + 1] += w * (a.y - t2 * b.y);
    }
}

// ---------------- kernels ----------------

// zero scratch; block 0 / warp 0 also detects int64 vs int32 index width
__global__ void k_zero(const void* adj, int T, int N) {
    int i = blockIdx.x * blockDim.x + threadIdx.x;
    if (blockIdx.x == 0 && threadIdx.x < 32) {
        int lane = threadIdx.x;
        int lim = (T < 32) ? T : 32;
        int bad = 0;
        if (lane < lim) {
            long long v = ((const long long*)adj)[lane];
            if (v < 0 || v >= (long long)N) bad = 1;
        }
        unsigned m = __ballot_sync(0xffffffffu, bad);
        if (lane == 0) g_flag64 = (m == 0u) ? 1 : 0;
    }
    if (i < T) g_tricode[i] = 0;
    if (i <= N) g_counts[i] = 0;
    if (i < N) g_cursor[i] = 0;
}

// fused: tri_rel scatter code + dst histogram
__global__ void k_prep(const void* r_tri, const void* r_rel,
                       const float* __restrict__ r_val, const void* adj, int T) {
    int t = blockIdx.x * blockDim.x + threadIdx.x;
    if (t >= T) return;
    long long seg = ld_idx(r_tri, t);
    long long rel = ld_idx(r_rel, t);
    float v = r_val[t];
    int code = 0;
    if (v > 0.0f)      code =  (int)rel + 1;
    else if (v < 0.0f) code = -((int)rel + 1);
    if (seg >= 0 && seg < T) g_tricode[seg] = code;
    long long dst = ld_idx(adj, t);
    atomicAdd(&g_counts[(int)dst], 1);
}

// ---- scan phase 1: per-chunk local exclusive prefix + chunk totals ----
__global__ void k_scan1(int N) {
    __shared__ int warpsum[8];
    int tid = threadIdx.x;
    int base = blockIdx.x * SCAN_CHUNK + tid * 8;
    int v[8];
    #pragma unroll
    for (int i = 0; i < 8; i++) {
        int j = base + i;
        v[i] = (j < N) ? g_counts[j] : 0;
    }
    int pref[8];
    int s = 0;
    #pragma unroll
    for (int i = 0; i < 8; i++) { pref[i] = s; s += v[i]; }
    int lane = tid & 31, w = tid >> 5;
    int inc = s;
    #pragma unroll
    for (int off = 1; off < 32; off <<= 1) {
        int t = __shfl_up_sync(0xffffffffu, inc, off);
        if (lane >= off) inc += t;
    }
    if (lane == 31) warpsum[w] = inc;
    __syncthreads();
    int woff = 0;
    #pragma unroll
    for (int k = 0; k < 7; k++) if (k < w) woff += warpsum[k];
    int toff = woff + inc - s;
    #pragma unroll
    for (int i = 0; i < 8; i++) {
        int j = base + i;
        if (j < N) g_rowptr[j] = toff + pref[i];
    }
    if (tid == 255) g_bsum[blockIdx.x] = woff + inc;
}

// ---- scan phase 2 (fused): add chunk-exclusive offsets ----
__global__ void k_scan3(int N, int nb) {
    __shared__ int s_off;
    int chunk = (blockIdx.x << 8) / SCAN_CHUNK;
    if (threadIdx.x < 32) {
        int b = threadIdx.x;
        int v = (b < nb) ? g_bsum[b] : 0;
        int contrib = (b < chunk) ? v : 0;
        #pragma unroll
        for (int off = 16; off; off >>= 1) contrib += __shfl_xor_sync(0xffffffffu, contrib, off);
        if (b == 0) s_off = contrib;
        if (blockIdx.x == 0) {
            int tot = v;
            #pragma unroll
            for (int off = 16; off; off >>= 1) tot += __shfl_xor_sync(0xffffffffu, tot, off);
            if (b == 0) g_rowptr[N] = tot;
        }
    }
    __syncthreads();
    int j = blockIdx.x * 256 + threadIdx.x;
    if (j < N) g_rowptr[j] += s_off;
}

__global__ void k_place(const void* adj, int T) {
    int t = blockIdx.x * blockDim.x + threadIdx.x;
    if (t >= T) return;
    int dst = (int)ld_idx(adj, t);
    int src = (int)ld_idx(adj, (long long)T + t);
    int pos = g_rowptr[dst] + atomicAdd(&g_cursor[dst], 1);
    int c = g_tricode[t];
    g_srcp[pos]    = src;
    g_relcode[pos] = c;
    g_reli[pos]    = c ? ((c > 0 ? c : -c) - 1) : -1;
}

// L2-normalize rel_emb rows (f32 math, fp16 store); per-relation attention logits.
__global__ void k_normalize(const float* __restrict__ rel_emb,
                            const float* __restrict__ attnk, int depth) {
    __shared__ float sm[32];
    int r = blockIdx.x;
    int d = threadIdx.x;
    float v = rel_emb[(size_t)r * DMAX + d];
    float ss = blockReduce256(v * v, sm);
    float scale = 1.0f / fmaxf(sqrtf(ss), 1e-12f);
    float nv = v * scale;
    g_nrel[(size_t)r * DMAX + d] = __float2half_rn(nv);
    for (int l = 0; l < depth; l++) {
        float a = blockReduce256(nv * attnk[(size_t)l * DMAX + d], sm);
        if (d == 0) g_attrel[l * RMAX + r] = a;
    }
}

// Precompute per-edge softmax weights for all layers. One warp per dst node.
__global__ void __launch_bounds__(256) k_weights(int N, int T, int depth) {
    int gw   = (blockIdx.x * blockDim.x + threadIdx.x) >> 5;
    int lane = threadIdx.x & 31;
    if (gw >= N) return;
    int e0 = g_rowptr[gw], e1 = g_rowptr[gw + 1];
    if (e0 >= e1) return;

    for (int l = 0; l < depth; l++) {
        const float* __restrict__ ar = g_attrel + l * RMAX;
        float m = -1e30f, s = 0.0f;
        for (int base = e0; base < e1; base += 32) {
            int e = base + lane;
            bool valid = e < e1;
            float a = 0.0f;
            if (valid) {
                int c = g_relcode[e];
                if (c) { int r = (c > 0 ? c : -c) - 1; a = ar[r]; if (c < 0) a = -a; }
            }
            float am = valid ? a : -1e30f;
            #pragma unroll
            for (int off = 16; off; off >>= 1) am = fmaxf(am, __shfl_xor_sync(0xffffffffu, am, off));
            float nm = fmaxf(m, am);
            float ex = valid ? expf(a - nm) : 0.0f;
            #pragma unroll
            for (int off = 16; off; off >>= 1) ex += __shfl_xor_sync(0xffffffffu, ex, off);
            s = s * expf(m - nm) + ex;
            m = nm;
        }
        float inv = 1.0f / s;
        for (int base = e0; base < e1; base += 32) {
            int e = base + lane;
            if (e < e1) {
                int c = g_relcode[e];
                float a = 0.0f;
                if (c) { int r = (c > 0 ? c : -c) - 1; a = ar[r]; if (c < 0) a = -a; }
                g_w[(size_t)l * T + e] = expf(a - m) * inv;
            }
        }
    }
}

// x0 = tanh(features); fp16 to ping buffer, exact f32 to output slice 0.
__global__ void k_tanh0(const float* __restrict__ f, float* __restrict__ out,
                        int N, int outd) {
    int i = blockIdx.x * blockDim.x + threadIdx.x;   // over N*32 groups of 8
    if (i >= N * 32) return;
    int row = i >> 5, grp = i & 31;
    const float4* src = (const float4*)(f + (size_t)row * DMAX) + grp * 2;
    float4 a = src[0], b = src[1];
    a.x = tanhf(a.x); a.y = tanhf(a.y); a.z = tanhf(a.z); a.w = tanhf(a.w);
    b.x = tanhf(b.x); b.y = tanhf(b.y); b.z = tanhf(b.z); b.w = tanhf(b.w);
    float4* ow = (float4*)(out + (size_t)row * outd) + grp * 2;
    ow[0] = a; ow[1] = b;
    float4 hraw;
    __half2* hh = (__half2*)&hraw;
    hh[0] = __floats2half2_rn(a.x, a.y);
    hh[1] = __floats2half2_rn(a.z, a.w);
    hh[2] = __floats2half2_rn(b.x, b.y);
    hh[3] = __floats2half2_rn(b.z, b.w);
    ((float4*)(g_xA + (size_t)row * DMAX))[grp] = hraw;
}

// One warp per destination node: reflected weighted aggregation (weights precomputed).
// 2-way unroll, packed fp16 operands, meta (src/rel/w) software-pipelined 1 iter ahead.
__global__ void __launch_bounds__(256)
k_layer(float* __restrict__ out, int outoff, int outd, int N, int T, int l,
        int inbuf_is_B, int write_next) {
    int gw   = (blockIdx.x * blockDim.x + threadIdx.x) >> 5;
    int lane = threadIdx.x & 31;
    if (gw >= N) return;
    const __half* __restrict__ xin = inbuf_is_B ? g_xB : g_xA;
    __half*       __restrict__ xnx = inbuf_is_B ? g_xA : g_xB;
    const float*  __restrict__ wrow = g_w + (size_t)l * T;

    int e0 = g_rowptr[gw], e1 = g_rowptr[gw + 1];
    float acc[8] = {0, 0, 0, 0, 0, 0, 0, 0};

    int e = e0;
    // preload first pair's meta so gather addresses are ready at loop entry
    int s0c = 0, s1c = 0, r0c = 0, r1c = 0;
    float w0c = 0.0f, w1c = 0.0f;
    if (e + 1 < e1) {
        s0c = g_srcp[e];     r0c = g_reli[e];     w0c = wrow[e];
        s1c = g_srcp[e + 1]; r1c = g_reli[e + 1]; w1c = wrow[e + 1];
    }
    for (; e + 1 < e1; e += 2) {
        // issue gathers immediately (addresses in registers)
        uint4 x0 = ((const uint4*)(xin + (size_t)s0c * DMAX))[lane];
        uint4 x1 = ((const uint4*)(xin + (size_t)s1c * DMAX))[lane];
        uint4 v0 = ((const uint4*)(g_nrel + (size_t)(r0c < 0 ? 0 : r0c) * DMAX))[lane];
        uint4 v1 = ((const uint4*)(g_nrel + (size_t)(r1c < 0 ? 0 : r1c) * DMAX))[lane];

        // prefetch next pair's meta while gathers + reduction are in flight
        int s0n = s0c, s1n = s1c, r0n = r0c, r1n = r1c;
        float w0n = w0c, w1n = w1c;
        if (e + 3 < e1) {
            s0n = g_srcp[e + 2]; r0n = g_reli[e + 2]; w0n = wrow[e + 2];
            s1n = g_srcp[e + 3]; r1n = g_reli[e + 3]; w1n = wrow[e + 3];
        }

        float p0 = dot8h(x0, v0);
        float p1 = dot8h(x1, v1);
        #pragma unroll
        for (int off = 16; off; off >>= 1) {
            p0 += __shfl_xor_sync(0xffffffffu, p0, off);
            p1 += __shfl_xor_sync(0xffffffffu, p1, off);
        }
        float t20 = (r0c >= 0) ? 2.0f * p0 : 0.0f;
        float t21 = (r1c >= 0) ? 2.0f * p1 : 0.0f;
        axpy8h(acc, w0c, t20, x0, v0);
        axpy8h(acc, w1c, t21, x1, v1);

        s0c = s0n; s1c = s1n; r0c = r0n; r1c = r1n; w0c = w0n; w1c = w1n;
    }
    for (; e < e1; e++) {
        int r = g_reli[e], srow = g_srcp[e];
        float w = wrow[e];
        uint4 x = ((const uint4*)(xin + (size_t)srow * DMAX))[lane];
        uint4 v = ((const uint4*)(g_nrel + (size_t)(r < 0 ? 0 : r) * DMAX))[lane];
        float p = dot8h(x, v);
        #pragma unroll
        for (int off = 16; off; off >>= 1) p += __shfl_xor_sync(0xffffffffu, p, off);
        float t2 = (r >= 0) ? 2.0f * p : 0.0f;
        axpy8h(acc, w, t2, x, v);
    }

    float o[8];
    #pragma unroll
    for (int i = 0; i < 8; i++) o[i] = tanhf(acc[i]);

    if (write_next) {
        float4 hraw;
        __half2* hh = (__half2*)&hraw;
        hh[0] = __floats2half2_rn(o[0], o[1]);
        hh[1] = __floats2half2_rn(o[2], o[3]);
        hh[2] = __floats2half2_rn(o[4], o[5]);
        hh[3] = __floats2half2_rn(o[6], o[7]);
        ((float4*)(xnx + (size_t)gw * DMAX))[lane] = hraw;
    }
    float4* ow = (float4*)(out + (size_t)gw * outd + outoff);
    ow[2 * lane]     = make_float4(o[0], o[1], o[2], o[3]);
    ow[2 * lane + 1] = make_float4(o[4], o[5], o[6], o[7]);
}

// ---------------- launch ----------------
extern "C" void kernel_launch(void* const* d_in, const int* in_sizes, int n_in,
                              void* d_out, int out_size) {
    const float* features = (const float*)d_in[0];
    const float* rel_emb  = (const float*)d_in[1];
    const float* attnk    = (const float*)d_in[2];
    const float* r_val    = (const float*)d_in[3];
    const void*  adj      = d_in[4];
    const void*  r_tri    = d_in[5];
    const void*  r_rel    = d_in[6];
    float* out = (float*)d_out;

    int N = in_sizes[0] / DMAX;
    int R = in_sizes[1] / DMAX;
    int depth = in_sizes[2] / DMAX;
    int T = in_sizes[3];
    if (N <= 0 || T <= 0) return;
    if (N > NMAX) N = NMAX;
    if (T > TMAX) T = TMAX;
    if (R > RMAX) R = RMAX;
    if (depth > DEPMAX) depth = DEPMAX;
    int outd = (depth + 1) * DMAX;

    int M = (T > N + 1) ? T : (N + 1);
    k_zero<<<(M + 255) / 256, 256>>>(adj, T, N);
    k_prep<<<(T + 255) / 256, 256>>>(r_tri, r_rel, r_val, adj, T);

    int nb = (N + SCAN_CHUNK - 1) / SCAN_CHUNK;   // <= 25 for NMAX
    k_scan1<<<nb, 256>>>(N);
    k_scan3<<<(N + 255) / 256, 256>>>(N, nb);

    k_place<<<(T + 255) / 256, 256>>>(adj, T);
    k_normalize<<<R, 256>>>(rel_emb, attnk, depth);

    int wblocks = (int)(((size_t)N * 32 + 255) / 256);
    k_weights<<<wblocks, 256>>>(N, T, depth);
    k_tanh0<<<((size_t)N * 32 + 255) / 256, 256>>>(features, out, N, outd);

    for (int l = 0; l < depth; l++) {
        int inbuf_is_B = (l & 1);
        int write_next = (l < depth - 1) ? 1 : 0;
        k_layer<<<wblocks, 256>>>(out, (l + 1) * DMAX, outd, N, T, l, inbuf_is_B, write_next);
    }
}

// round 14
// speedup vs baseline: 1.1370x; 1.1370x over previous
#include <cuda_runtime.h>
#include <cuda_fp16.h>
#include <math.h>

#define DMAX   256
#define NMAX   50000
#define TMAX   400000
#define RMAX   1000
#define DEPMAX 2
#define ESPAN  (2 * RMAX + 1)   // expa table: index = code + RMAX, code in [-R, R]
#define SCAN_CHUNK 2048          // elements per scan block (256 thr * 8)

// ---------------- static device scratch (no allocation allowed) ----------------
__device__ __align__(16) __half g_xA[(size_t)NMAX * DMAX];    // 25.6 MB
__device__ __align__(16) __half g_xB[(size_t)NMAX * DMAX];    // 25.6 MB
__device__ __align__(16) __half g_nrel[(size_t)RMAX * DMAX];  // 512 KB
__device__ float g_attrel[DEPMAX * RMAX];
__device__ float g_expa[DEPMAX * ESPAN];       // exp(a - mg) per signed code per layer
__device__ int   g_mgbits[DEPMAX];             // per-layer max|a| as float bits
__device__ float g_w[(size_t)DEPMAX * TMAX];   // per-edge softmax weights per layer
__device__ int   g_counts[NMAX + 1];
__device__ int   g_rowptr[NMAX + 1];
__device__ int   g_cursor[NMAX];
__device__ int   g_bsum[64];
__device__ int   g_srcp[TMAX];
__device__ int   g_reli[TMAX];      // relation index per CSR edge, -1 if zero tri_rel
__device__ int   g_relcode[TMAX];   // signed code per CSR edge: 0 or +-(rel+1)
__device__ int   g_tricode[TMAX];   // per-triple code before CSR permutation
__device__ int   g_flag64;          // 1 if index arrays are int64, 0 if int32

// ---------------- helpers ----------------
__device__ __forceinline__ long long ld_idx(const void* p, long long i) {
    return g_flag64 ? ((const long long*)p)[i] : (long long)((const int*)p)[i];
}

__device__ __forceinline__ float blockReduce256(float v, float* sm) {
    #pragma unroll
    for (int off = 16; off; off >>= 1) v += __shfl_xor_sync(0xffffffffu, v, off);
    int w = threadIdx.x >> 5;
    if ((threadIdx.x & 31) == 0) sm[w] = v;
    __syncthreads();
    if (threadIdx.x < 32) {
        float r = (threadIdx.x < 8) ? sm[threadIdx.x] : 0.0f;
        #pragma unroll
        for (int off = 4; off; off >>= 1) r += __shfl_xor_sync(0xffffffffu, r, off);
        if (threadIdx.x == 0) sm[0] = r;
    }
    __syncthreads();
    float res = sm[0];
    __syncthreads();
    return res;
}

// dot of 8 fp16 pairs held as raw uint4 (convert on the fly, f32 fma accumulate)
__device__ __forceinline__ float dot8h(const uint4& xr, const uint4& vr) {
    const __half2* hx = (const __half2*)&xr;
    const __half2* hv = (const __half2*)&vr;
    float p = 0.0f;
    #pragma unroll
    for (int i = 0; i < 4; i++) {
        float2 a = __half22float2(hx[i]);
        float2 b = __half22float2(hv[i]);
        p = fmaf(a.x, b.x, p);
        p = fmaf(a.y, b.y, p);
    }
    return p;
}

// acc += w * (x - t2 * v), operands raw fp16
__device__ __forceinline__ void axpy8h(float acc[8], float w, float t2,
                                       const uint4& xr, const uint4& vr) {
    const __half2* hx = (const __half2*)&xr;
    const __half2* hv = (const __half2*)&vr;
    #pragma unroll
    for (int i = 0; i < 4; i++) {
        float2 a = __half22float2(hx[i]);
        float2 b = __half22float2(hv[i]);
        acc[2 * i]     += w * (a.x - t2 * b.x);
        acc[2 * i + 1] += w * (a.y - t2 * b.y);
    }
}

// ---------------- kernels ----------------

// zero scratch; block 0 / warp 0 also detects int64 vs int32 index width
__global__ void k_zero(const void* adj, int T, int N) {
    int i = blockIdx.x * blockDim.x + threadIdx.x;
    if (blockIdx.x == 0 && threadIdx.x < 32) {
        int lane = threadIdx.x;
        int lim = (T < 32) ? T : 32;
        int bad = 0;
        if (lane < lim) {
            long long v = ((const long long*)adj)[lane];
            if (v < 0 || v >= (long long)N) bad = 1;
        }
        unsigned m = __ballot_sync(0xffffffffu, bad);
        if (lane == 0) g_flag64 = (m == 0u) ? 1 : 0;
    }
    if (i < DEPMAX) g_mgbits[i] = 0;
    if (i < T) g_tricode[i] = 0;
    if (i <= N) g_counts[i] = 0;
    if (i < N) g_cursor[i] = 0;
}

// fused: tri_rel scatter code + dst histogram
__global__ void k_prep(const void* r_tri, const void* r_rel,
                       const float* __restrict__ r_val, const void* adj, int T) {
    int t = blockIdx.x * blockDim.x + threadIdx.x;
    if (t >= T) return;
    long long seg = ld_idx(r_tri, t);
    long long rel = ld_idx(r_rel, t);
    float v = r_val[t];
    int code = 0;
    if (v > 0.0f)      code =  (int)rel + 1;
    else if (v < 0.0f) code = -((int)rel + 1);
    if (seg >= 0 && seg < T) g_tricode[seg] = code;
    long long dst = ld_idx(adj, t);
    atomicAdd(&g_counts[(int)dst], 1);
}

// ---- scan phase 1: per-chunk local exclusive prefix + chunk totals ----
__global__ void k_scan1(int N) {
    __shared__ int warpsum[8];
    int tid = threadIdx.x;
    int base = blockIdx.x * SCAN_CHUNK + tid * 8;
    int v[8];
    #pragma unroll
    for (int i = 0; i < 8; i++) {
        int j = base + i;
        v[i] = (j < N) ? g_counts[j] : 0;
    }
    int pref[8];
    int s = 0;
    #pragma unroll
    for (int i = 0; i < 8; i++) { pref[i] = s; s += v[i]; }
    int lane = tid & 31, w = tid >> 5;
    int inc = s;
    #pragma unroll
    for (int off = 1; off < 32; off <<= 1) {
        int t = __shfl_up_sync(0xffffffffu, inc, off);
        if (lane >= off) inc += t;
    }
    if (lane == 31) warpsum[w] = inc;
    __syncthreads();
    int woff = 0;
    #pragma unroll
    for (int k = 0; k < 7; k++) if (k < w) woff += warpsum[k];
    int toff = woff + inc - s;
    #pragma unroll
    for (int i = 0; i < 8; i++) {
        int j = base + i;
        if (j < N) g_rowptr[j] = toff + pref[i];
    }
    if (tid == 255) g_bsum[blockIdx.x] = woff + inc;
}

// ---- scan phase 2 (fused): add chunk-exclusive offsets ----
__global__ void k_scan3(int N, int nb) {
    __shared__ int s_off;
    int chunk = (blockIdx.x << 8) / SCAN_CHUNK;
    if (threadIdx.x < 32) {
        int b = threadIdx.x;
        int v = (b < nb) ? g_bsum[b] : 0;
        int contrib = (b < chunk) ? v : 0;
        #pragma unroll
        for (int off = 16; off; off >>= 1) contrib += __shfl_xor_sync(0xffffffffu, contrib, off);
        if (b == 0) s_off = contrib;
        if (blockIdx.x == 0) {
            int tot = v;
            #pragma unroll
            for (int off = 16; off; off >>= 1) tot += __shfl_xor_sync(0xffffffffu, tot, off);
            if (b == 0) g_rowptr[N] = tot;
        }
    }
    __syncthreads();
    int j = blockIdx.x * 256 + threadIdx.x;
    if (j < N) g_rowptr[j] += s_off;
}

__global__ void k_place(const void* adj, int T) {
    int t = blockIdx.x * blockDim.x + threadIdx.x;
    if (t >= T) return;
    int dst = (int)ld_idx(adj, t);
    int src = (int)ld_idx(adj, (long long)T + t);
    int pos = g_rowptr[dst] + atomicAdd(&g_cursor[dst], 1);
    int c = g_tricode[t];
    g_srcp[pos]    = src;
    g_relcode[pos] = c;
    g_reli[pos]    = c ? ((c > 0 ? c : -c) - 1) : -1;
}

// L2-normalize rel_emb rows (f32 math, fp16 store); logits + per-layer max|a|.
__global__ void k_normalize(const float* __restrict__ rel_emb,
                            const float* __restrict__ attnk, int depth) {
    __shared__ float sm[32];
    int r = blockIdx.x;
    int d = threadIdx.x;
    float v = rel_emb[(size_t)r * DMAX + d];
    float ss = blockReduce256(v * v, sm);
    float scale = 1.0f / fmaxf(sqrtf(ss), 1e-12f);
    float nv = v * scale;
    g_nrel[(size_t)r * DMAX + d] = __float2half_rn(nv);
    for (int l = 0; l < depth; l++) {
        float a = blockReduce256(nv * attnk[(size_t)l * DMAX + d], sm);
        if (d == 0) {
            g_attrel[l * RMAX + r] = a;
            atomicMax(&g_mgbits[l], __float_as_int(fabsf(a)));  // |a| >= 0: int cmp ok
        }
    }
}

// tabulate exp(a(code) - mg) for code in [-R, R]; table index = code + RMAX
__global__ void k_expa(int R, int depth) {
    int i = blockIdx.x * blockDim.x + threadIdx.x;
    if (i >= depth * ESPAN) return;
    int l = i / ESPAN, j = i % ESPAN;
    int code = j - RMAX;                 // signed code
    float a = 0.0f;
    if (code > 0 && code <= R)        a =  g_attrel[l * RMAX + (code - 1)];
    else if (code < 0 && -code <= R)  a = -g_attrel[l * RMAX + (-code - 1)];
    else if (code != 0)               { g_expa[l * ESPAN + j] = 0.0f; return; }
    float mg = __int_as_float(g_mgbits[l]);
    g_expa[l * ESPAN + j] = expf(a - mg);
}

// Per-edge softmax weights for ALL layers: one sum pass + one write pass.
// Table-lookup replaces expf; global-offset softmax is shift-invariant.
__global__ void __launch_bounds__(256) k_weights(int N, int T, int depth) {
    int gw   = (blockIdx.x * blockDim.x + threadIdx.x) >> 5;
    int lane = threadIdx.x & 31;
    if (gw >= N) return;
    int e0 = g_rowptr[gw], e1 = g_rowptr[gw + 1];
    if (e0 >= e1) return;

    float s0 = 0.0f, s1 = 0.0f;
    for (int e = e0 + lane; e < e1; e += 32) {
        int j = g_relcode[e] + RMAX;
        s0 += g_expa[j];
        if (depth > 1) s1 += g_expa[ESPAN + j];
    }
    #pragma unroll
    for (int off = 16; off; off >>= 1) {
        s0 += __shfl_xor_sync(0xffffffffu, s0, off);
        s1 += __shfl_xor_sync(0xffffffffu, s1, off);
    }
    float i0 = 1.0f / s0;
    float i1 = (depth > 1) ? 1.0f / s1 : 0.0f;
    for (int e = e0 + lane; e < e1; e += 32) {
        int j = g_relcode[e] + RMAX;
        g_w[e] = g_expa[j] * i0;
        if (depth > 1) g_w[(size_t)T + e] = g_expa[ESPAN + j] * i1;
    }
}

// x0 = tanh(features); fp16 to ping buffer, exact f32 to output slice 0.
__global__ void k_tanh0(const float* __restrict__ f, float* __restrict__ out,
                        int N, int outd) {
    int i = blockIdx.x * blockDim.x + threadIdx.x;   // over N*32 groups of 8
    if (i >= N * 32) return;
    int row = i >> 5, grp = i & 31;
    const float4* src = (const float4*)(f + (size_t)row * DMAX) + grp * 2;
    float4 a = src[0], b = src[1];
    a.x = tanhf(a.x); a.y = tanhf(a.y); a.z = tanhf(a.z); a.w = tanhf(a.w);
    b.x = tanhf(b.x); b.y = tanhf(b.y); b.z = tanhf(b.z); b.w = tanhf(b.w);
    float4* ow = (float4*)(out + (size_t)row * outd) + grp * 2;
    ow[0] = a; ow[1] = b;
    float4 hraw;
    __half2* hh = (__half2*)&hraw;
    hh[0] = __floats2half2_rn(a.x, a.y);
    hh[1] = __floats2half2_rn(a.z, a.w);
    hh[2] = __floats2half2_rn(b.x, b.y);
    hh[3] = __floats2half2_rn(b.z, b.w);
    ((float4*)(g_xA + (size_t)row * DMAX))[grp] = hraw;
}

// One warp per destination node: reflected weighted aggregation (weights precomputed).
// 2-way unroll, packed fp16 operands — frozen R12 body (local optimum).
__global__ void __launch_bounds__(256)
k_layer(float* __restrict__ out, int outoff, int outd, int N, int T, int l,
        int inbuf_is_B, int write_next) {
    int gw   = (blockIdx.x * blockDim.x + threadIdx.x) >> 5;
    int lane = threadIdx.x & 31;
    if (gw >= N) return;
    const __half* __restrict__ xin = inbuf_is_B ? g_xB : g_xA;
    __half*       __restrict__ xnx = inbuf_is_B ? g_xA : g_xB;
    const float*  __restrict__ wrow = g_w + (size_t)l * T;

    int e0 = g_rowptr[gw], e1 = g_rowptr[gw + 1];
    float acc[8] = {0, 0, 0, 0, 0, 0, 0, 0};

    int e = e0;
    // 2-way unrolled: overlap the two SHFL dot-reduction chains
    for (; e + 1 < e1; e += 2) {
        int r0 = g_reli[e],     s0 = g_srcp[e];     float w0 = wrow[e];
        int r1 = g_reli[e + 1], s1 = g_srcp[e + 1]; float w1 = wrow[e + 1];
        uint4 x0 = ((const uint4*)(xin + (size_t)s0 * DMAX))[lane];
        uint4 x1 = ((const uint4*)(xin + (size_t)s1 * DMAX))[lane];
        uint4 v0 = ((const uint4*)(g_nrel + (size_t)(r0 < 0 ? 0 : r0) * DMAX))[lane];
        uint4 v1 = ((const uint4*)(g_nrel + (size_t)(r1 < 0 ? 0 : r1) * DMAX))[lane];
        float p0 = dot8h(x0, v0);
        float p1 = dot8h(x1, v1);
        #pragma unroll
        for (int off = 16; off; off >>= 1) {
            p0 += __shfl_xor_sync(0xffffffffu, p0, off);
            p1 += __shfl_xor_sync(0xffffffffu, p1, off);
        }
        float t20 = (r0 >= 0) ? 2.0f * p0 : 0.0f;
        float t21 = (r1 >= 0) ? 2.0f * p1 : 0.0f;
        axpy8h(acc, w0, t20, x0, v0);
        axpy8h(acc, w1, t21, x1, v1);
    }
    for (; e < e1; e++) {
        int r = g_reli[e], srow = g_srcp[e];
        float w = wrow[e];
        uint4 x = ((const uint4*)(xin + (size_t)srow * DMAX))[lane];
        uint4 v = ((const uint4*)(g_nrel + (size_t)(r < 0 ? 0 : r) * DMAX))[lane];
        float p = dot8h(x, v);
        #pragma unroll
        for (int off = 16; off; off >>= 1) p += __shfl_xor_sync(0xffffffffu, p, off);
        float t2 = (r >= 0) ? 2.0f * p : 0.0f;
        axpy8h(acc, w, t2, x, v);
    }

    float o[8];
    #pragma unroll
    for (int i = 0; i < 8; i++) o[i] = tanhf(acc[i]);

    if (write_next) {
        float4 hraw;
        __half2* hh = (__half2*)&hraw;
        hh[0] = __floats2half2_rn(o[0], o[1]);
        hh[1] = __floats2half2_rn(o[2], o[3]);
        hh[2] = __floats2half2_rn(o[4], o[5]);
        hh[3] = __floats2half2_rn(o[6], o[7]);
        ((float4*)(xnx + (size_t)gw * DMAX))[lane] = hraw;
    }
    float4* ow = (float4*)(out + (size_t)gw * outd + outoff);
    ow[2 * lane]     = make_float4(o[0], o[1], o[2], o[3]);
    ow[2 * lane + 1] = make_float4(o[4], o[5], o[6], o[7]);
}

// ---------------- launch ----------------
extern "C" void kernel_launch(void* const* d_in, const int* in_sizes, int n_in,
                              void* d_out, int out_size) {
    const float* features = (const float*)d_in[0];
    const float* rel_emb  = (const float*)d_in[1];
    const float* attnk    = (const float*)d_in[2];
    const float* r_val    = (const float*)d_in[3];
    const void*  adj      = d_in[4];
    const void*  r_tri    = d_in[5];
    const void*  r_rel    = d_in[6];
    float* out = (float*)d_out;

    int N = in_sizes[0] / DMAX;
    int R = in_sizes[1] / DMAX;
    int depth = in_sizes[2] / DMAX;
    int T = in_sizes[3];
    if (N <= 0 || T <= 0) return;
    if (N > NMAX) N = NMAX;
    if (T > TMAX) T = TMAX;
    if (R > RMAX) R = RMAX;
    if (depth > DEPMAX) depth = DEPMAX;
    int outd = (depth + 1) * DMAX;

    int M = (T > N + 1) ? T : (N + 1);
    k_zero<<<(M + 255) / 256, 256>>>(adj, T, N);
    k_prep<<<(T + 255) / 256, 256>>>(r_tri, r_rel, r_val, adj, T);

    int nb = (N + SCAN_CHUNK - 1) / SCAN_CHUNK;   // <= 25 for NMAX
    k_scan1<<<nb, 256>>>(N);
    k_scan3<<<(N + 255) / 256, 256>>>(N, nb);

    k_place<<<(T + 255) / 256, 256>>>(adj, T);
    k_normalize<<<R, 256>>>(rel_emb, attnk, depth);
    k_expa<<<(depth * ESPAN + 255) / 256, 256>>>(R, depth);

    int wblocks = (int)(((size_t)N * 32 + 255) / 256);
    k_weights<<<wblocks, 256>>>(N, T, depth);
    k_tanh0<<<((size_t)N * 32 + 255) / 256, 256>>>(features, out, N, outd);

    for (int l = 0; l < depth; l++) {
        int inbuf_is_B = (l & 1);
        int write_next = (l < depth - 1) ? 1 : 0;
        k_layer<<<wblocks, 256>>>(out, (l + 1) * DMAX, outd, N, T, l, inbuf_is_B, write_next);
    }
}

// round 15
// speedup vs baseline: 1.1666x; 1.0260x over previous
#include <cuda_runtime.h>
#include <cuda_fp16.h>
#include <math.h>

#define DMAX   256
#define NMAX   50000
#define TMAX   400000
#define RMAX   1000
#define DEPMAX 2
#define ESPAN  (2 * RMAX + 1)   // expa table: index = idx, idx in [0, 2R]
#define SCAN_CHUNK 2048          // elements per scan block (256 thr * 8)

// ---------------- static device scratch (no allocation allowed) ----------------
__device__ __align__(16) __half g_xA[(size_t)NMAX * DMAX];    // 25.6 MB
__device__ __align__(16) __half g_xB[(size_t)NMAX * DMAX];    // 25.6 MB
__device__ __align__(16) __half g_nrel[(size_t)RMAX * DMAX];  // 512 KB
__device__ float g_attrel[DEPMAX * RMAX];
__device__ float g_expa[DEPMAX * ESPAN];       // exp(a - mg) per idx per layer
__device__ int   g_mgbits[DEPMAX];             // per-layer max|a| as float bits
__device__ float g_w[(size_t)DEPMAX * TMAX];   // per-edge softmax weights per layer
__device__ int   g_counts[NMAX + 1];
__device__ int   g_rowptr[NMAX + 1];
__device__ int   g_cursor[NMAX];
__device__ int   g_bsum[64];
__device__ unsigned g_meta[TMAX];   // CSR edge: src | (idx << 17); idx: 0=none, 1..R=+rel, R+1..2R=-rel
__device__ int   g_tricode[TMAX];   // per-triple idx before CSR permutation
__device__ int   g_flag64;          // 1 if index arrays are int64, 0 if int32

// ---------------- helpers ----------------
__device__ __forceinline__ long long ld_idx(const void* p, long long i) {
    return g_flag64 ? ((const long long*)p)[i] : (long long)((const int*)p)[i];
}

__device__ __forceinline__ float blockReduce256(float v, float* sm) {
    #pragma unroll
    for (int off = 16; off; off >>= 1) v += __shfl_xor_sync(0xffffffffu, v, off);
    int w = threadIdx.x >> 5;
    if ((threadIdx.x & 31) == 0) sm[w] = v;
    __syncthreads();
    if (threadIdx.x < 32) {
        float r = (threadIdx.x < 8) ? sm[threadIdx.x] : 0.0f;
        #pragma unroll
        for (int off = 4; off; off >>= 1) r += __shfl_xor_sync(0xffffffffu, r, off);
        if (threadIdx.x == 0) sm[0] = r;
    }
    __syncthreads();
    float res = sm[0];
    __syncthreads();
    return res;
}

// dot of 8 fp16 pairs held as raw uint4 (convert on the fly, f32 fma accumulate)
__device__ __forceinline__ float dot8h(const uint4& xr, const uint4& vr) {
    const __half2* hx = (const __half2*)&xr;
    const __half2* hv = (const __half2*)&vr;
    float p = 0.0f;
    #pragma unroll
    for (int i = 0; i < 4; i++) {
        float2 a = __half22float2(hx[i]);
        float2 b = __half22float2(hv[i]);
        p = fmaf(a.x, b.x, p);
        p = fmaf(a.y, b.y, p);
    }
    return p;
}

// acc += w * (x - t2 * v), operands raw fp16
__device__ __forceinline__ void axpy8h(float acc[8], float w, float t2,
                                       const uint4& xr, const uint4& vr) {
    const __half2* hx = (const __half2*)&xr;
    const __half2* hv = (const __half2*)&vr;
    #pragma unroll
    for (int i = 0; i < 4; i++) {
        float2 a = __half22float2(hx[i]);
        float2 b = __half22float2(hv[i]);
        acc[2 * i]     += w * (a.x - t2 * b.x);
        acc[2 * i + 1] += w * (a.y - t2 * b.y);
    }
}

// ---------------- kernels ----------------

// zero scratch; block 0 / warp 0 also detects int64 vs int32 index width
__global__ void k_zero(const void* adj, int T, int N) {
    int i = blockIdx.x * blockDim.x + threadIdx.x;
    if (blockIdx.x == 0 && threadIdx.x < 32) {
        int lane = threadIdx.x;
        int lim = (T < 32) ? T : 32;
        int bad = 0;
        if (lane < lim) {
            long long v = ((const long long*)adj)[lane];
            if (v < 0 || v >= (long long)N) bad = 1;
        }
        unsigned m = __ballot_sync(0xffffffffu, bad);
        if (lane == 0) g_flag64 = (m == 0u) ? 1 : 0;
    }
    if (i < DEPMAX) g_mgbits[i] = 0;
    if (i < T) g_tricode[i] = 0;
    if (i <= N) g_counts[i] = 0;
    if (i < N) g_cursor[i] = 0;
}

// fused: tri_rel idx scatter + dst histogram
// idx: 0 = zero tri_rel; [1,R] = +rel; [R+1,2R] = -rel
__global__ void k_prep(const void* r_tri, const void* r_rel,
                       const float* __restrict__ r_val, const void* adj, int T, int R) {
    int t = blockIdx.x * blockDim.x + threadIdx.x;
    if (t >= T) return;
    long long seg = ld_idx(r_tri, t);
    long long rel = ld_idx(r_rel, t);
    float v = r_val[t];
    int idx = 0;
    if (v > 0.0f)      idx = (int)rel + 1;
    else if (v < 0.0f) idx = R + (int)rel + 1;
    if (seg >= 0 && seg < T) g_tricode[seg] = idx;
    long long dst = ld_idx(adj, t);
    atomicAdd(&g_counts[(int)dst], 1);
}

// ---- scan phase 1: per-chunk local exclusive prefix + chunk totals ----
__global__ void k_scan1(int N) {
    __shared__ int warpsum[8];
    int tid = threadIdx.x;
    int base = blockIdx.x * SCAN_CHUNK + tid * 8;
    int v[8];
    #pragma unroll
    for (int i = 0; i < 8; i++) {
        int j = base + i;
        v[i] = (j < N) ? g_counts[j] : 0;
    }
    int pref[8];
    int s = 0;
    #pragma unroll
    for (int i = 0; i < 8; i++) { pref[i] = s; s += v[i]; }
    int lane = tid & 31, w = tid >> 5;
    int inc = s;
    #pragma unroll
    for (int off = 1; off < 32; off <<= 1) {
        int t = __shfl_up_sync(0xffffffffu, inc, off);
        if (lane >= off) inc += t;
    }
    if (lane == 31) warpsum[w] = inc;
    __syncthreads();
    int woff = 0;
    #pragma unroll
    for (int k = 0; k < 7; k++) if (k < w) woff += warpsum[k];
    int toff = woff + inc - s;
    #pragma unroll
    for (int i = 0; i < 8; i++) {
        int j = base + i;
        if (j < N) g_rowptr[j] = toff + pref[i];
    }
    if (tid == 255) g_bsum[blockIdx.x] = woff + inc;
}

// ---- scan phase 2 (fused): add chunk-exclusive offsets ----
__global__ void k_scan3(int N, int nb) {
    __shared__ int s_off;
    int chunk = (blockIdx.x << 8) / SCAN_CHUNK;
    if (threadIdx.x < 32) {
        int b = threadIdx.x;
        int v = (b < nb) ? g_bsum[b] : 0;
        int contrib = (b < chunk) ? v : 0;
        #pragma unroll
        for (int off = 16; off; off >>= 1) contrib += __shfl_xor_sync(0xffffffffu, contrib, off);
        if (b == 0) s_off = contrib;
        if (blockIdx.x == 0) {
            int tot = v;
            #pragma unroll
            for (int off = 16; off; off >>= 1) tot += __shfl_xor_sync(0xffffffffu, tot, off);
            if (b == 0) g_rowptr[N] = tot;
        }
    }
    __syncthreads();
    int j = blockIdx.x * 256 + threadIdx.x;
    if (j < N) g_rowptr[j] += s_off;
}

// single packed scattered store per edge
__global__ void k_place(const void* adj, int T) {
    int t = blockIdx.x * blockDim.x + threadIdx.x;
    if (t >= T) return;
    int dst = (int)ld_idx(adj, t);
    int src = (int)ld_idx(adj, (long long)T + t);
    int pos = g_rowptr[dst] + atomicAdd(&g_cursor[dst], 1);
    g_meta[pos] = (unsigned)src | ((unsigned)g_tricode[t] << 17);
}

// L2-normalize rel_emb rows (f32 math, fp16 store); logits + per-layer max|a|.
__global__ void k_normalize(const float* __restrict__ rel_emb,
                            const float* __restrict__ attnk, int depth) {
    __shared__ float sm[32];
    int r = blockIdx.x;
    int d = threadIdx.x;
    float v = rel_emb[(size_t)r * DMAX + d];
    float ss = blockReduce256(v * v, sm);
    float scale = 1.0f / fmaxf(sqrtf(ss), 1e-12f);
    float nv = v * scale;
    g_nrel[(size_t)r * DMAX + d] = __float2half_rn(nv);
    for (int l = 0; l < depth; l++) {
        float a = blockReduce256(nv * attnk[(size_t)l * DMAX + d], sm);
        if (d == 0) {
            g_attrel[l * RMAX + r] = a;
            atomicMax(&g_mgbits[l], __float_as_int(fabsf(a)));  // |a| >= 0: int cmp ok
        }
    }
}

// tabulate exp(a(idx) - mg) for idx in [0, 2R]
__global__ void k_expa(int R, int depth) {
    int i = blockIdx.x * blockDim.x + threadIdx.x;
    if (i >= depth * ESPAN) return;
    int l = i / ESPAN, j = i % ESPAN;
    float a = 0.0f;
    if (j >= 1 && j <= R)              a =  g_attrel[l * RMAX + (j - 1)];
    else if (j > R && j <= 2 * R)      a = -g_attrel[l * RMAX + (j - R - 1)];
    else if (j != 0)                   { g_expa[l * ESPAN + j] = 0.0f; return; }
    float mg = __int_as_float(g_mgbits[l]);
    g_expa[l * ESPAN + j] = expf(a - mg);
}

// Per-edge softmax weights for ALL layers: one sum pass + one write pass.
__global__ void __launch_bounds__(256) k_weights(int N, int T, int depth) {
    int gw   = (blockIdx.x * blockDim.x + threadIdx.x) >> 5;
    int lane = threadIdx.x & 31;
    if (gw >= N) return;
    int e0 = g_rowptr[gw], e1 = g_rowptr[gw + 1];
    if (e0 >= e1) return;

    float s0 = 0.0f, s1 = 0.0f;
    for (int e = e0 + lane; e < e1; e += 32) {
        unsigned j = g_meta[e] >> 17;
        s0 += g_expa[j];
        if (depth > 1) s1 += g_expa[ESPAN + j];
    }
    #pragma unroll
    for (int off = 16; off; off >>= 1) {
        s0 += __shfl_xor_sync(0xffffffffu, s0, off);
        s1 += __shfl_xor_sync(0xffffffffu, s1, off);
    }
    float i0 = 1.0f / s0;
    float i1 = (depth > 1) ? 1.0f / s1 : 0.0f;
    for (int e = e0 + lane; e < e1; e += 32) {
        unsigned j = g_meta[e] >> 17;
        g_w[e] = g_expa[j] * i0;
        if (depth > 1) g_w[(size_t)T + e] = g_expa[ESPAN + j] * i1;
    }
}

// x0 = tanh(features); fp16 to ping buffer, exact f32 to output slice 0.
__global__ void k_tanh0(const float* __restrict__ f, float* __restrict__ out,
                        int N, int outd) {
    int i = blockIdx.x * blockDim.x + threadIdx.x;   // over N*32 groups of 8
    if (i >= N * 32) return;
    int row = i >> 5, grp = i & 31;
    const float4* src = (const float4*)(f + (size_t)row * DMAX) + grp * 2;
    float4 a = src[0], b = src[1];
    a.x = tanhf(a.x); a.y = tanhf(a.y); a.z = tanhf(a.z); a.w = tanhf(a.w);
    b.x = tanhf(b.x); b.y = tanhf(b.y); b.z = tanhf(b.z); b.w = tanhf(b.w);
    float4* ow = (float4*)(out + (size_t)row * outd) + grp * 2;
    ow[0] = a; ow[1] = b;
    float4 hraw;
    __half2* hh = (__half2*)&hraw;
    hh[0] = __floats2half2_rn(a.x, a.y);
    hh[1] = __floats2half2_rn(a.z, a.w);
    hh[2] = __floats2half2_rn(b.x, b.y);
    hh[3] = __floats2half2_rn(b.z, b.w);
    ((float4*)(g_xA + (size_t)row * DMAX))[grp] = hraw;
}

// One warp per destination node: reflected weighted aggregation (weights precomputed).
// 2-way unroll, packed fp16 operands; per-edge meta is ONE packed load + ALU decode.
__global__ void __launch_bounds__(256)
k_layer(float* __restrict__ out, int outoff, int outd, int N, int T, int R, int l,
        int inbuf_is_B, int write_next) {
    int gw   = (blockIdx.x * blockDim.x + threadIdx.x) >> 5;
    int lane = threadIdx.x & 31;
    if (gw >= N) return;
    const __half* __restrict__ xin = inbuf_is_B ? g_xB : g_xA;
    __half*       __restrict__ xnx = inbuf_is_B ? g_xA : g_xB;
    const float*  __restrict__ wrow = g_w + (size_t)l * T;

    int e0 = g_rowptr[gw], e1 = g_rowptr[gw + 1];
    float acc[8] = {0, 0, 0, 0, 0, 0, 0, 0};

    int e = e0;
    // 2-way unrolled: overlap the two SHFL dot-reduction chains
    for (; e + 1 < e1; e += 2) {
        unsigned m0 = g_meta[e], m1 = g_meta[e + 1];
        float w0 = wrow[e], w1 = wrow[e + 1];
        unsigned s0 = m0 & 0x1FFFFu, s1 = m1 & 0x1FFFFu;
        unsigned i0 = m0 >> 17,      i1 = m1 >> 17;
        int r0 = (i0 > (unsigned)R) ? (int)(i0 - R - 1) : (int)i0 - 1;  // -1 if i0==0
        int r1 = (i1 > (unsigned)R) ? (int)(i1 - R - 1) : (int)i1 - 1;
        uint4 x0 = ((const uint4*)(xin + (size_t)s0 * DMAX))[lane];
        uint4 x1 = ((const uint4*)(xin + (size_t)s1 * DMAX))[lane];
        uint4 v0 = ((const uint4*)(g_nrel + (size_t)(r0 < 0 ? 0 : r0) * DMAX))[lane];
        uint4 v1 = ((const uint4*)(g_nrel + (size_t)(r1 < 0 ? 0 : r1) * DMAX))[lane];
        float p0 = dot8h(x0, v0);
        float p1 = dot8h(x1, v1);
        #pragma unroll
        for (int off = 16; off; off >>= 1) {
            p0 += __shfl_xor_sync(0xffffffffu, p0, off);
            p1 += __shfl_xor_sync(0xffffffffu, p1, off);
        }
        float t20 = (r0 >= 0) ? 2.0f * p0 : 0.0f;
        float t21 = (r1 >= 0) ? 2.0f * p1 : 0.0f;
        axpy8h(acc, w0, t20, x0, v0);
        axpy8h(acc, w1, t21, x1, v1);
    }
    for (; e < e1; e++) {
        unsigned m = g_meta[e];
        float w = wrow[e];
        unsigned sr = m & 0x1FFFFu;
        unsigned ix = m >> 17;
        int r = (ix > (unsigned)R) ? (int)(ix - R - 1) : (int)ix - 1;
        uint4 x = ((const uint4*)(xin + (size_t)sr * DMAX))[lane];
        uint4 v = ((const uint4*)(g_nrel + (size_t)(r < 0 ? 0 : r) * DMAX))[lane];
        float p = dot8h(x, v);
        #pragma unroll
        for (int off = 16; off; off >>= 1) p += __shfl_xor_sync(0xffffffffu, p, off);
        float t2 = (r >= 0) ? 2.0f * p : 0.0f;
        axpy8h(acc, w, t2, x, v);
    }

    float o[8];
    #pragma unroll
    for (int i = 0; i < 8; i++) o[i] = tanhf(acc[i]);

    if (write_next) {
        float4 hraw;
        __half2* hh = (__half2*)&hraw;
        hh[0] = __floats2half2_rn(o[0], o[1]);
        hh[1] = __floats2half2_rn(o[2], o[3]);
        hh[2] = __floats2half2_rn(o[4], o[5]);
        hh[3] = __floats2half2_rn(o[6], o[7]);
        ((float4*)(xnx + (size_t)gw * DMAX))[lane] = hraw;
    }
    float4* ow = (float4*)(out + (size_t)gw * outd + outoff);
    ow[2 * lane]     = make_float4(o[0], o[1], o[2], o[3]);
    ow[2 * lane + 1] = make_float4(o[4], o[5], o[6], o[7]);
}

// ---------------- launch ----------------
extern "C" void kernel_launch(void* const* d_in, const int* in_sizes, int n_in,
                              void* d_out, int out_size) {
    const float* features = (const float*)d_in[0];
    const float* rel_emb  = (const float*)d_in[1];
    const float* attnk    = (const float*)d_in[2];
    const float* r_val    = (const float*)d_in[3];
    const void*  adj      = d_in[4];
    const void*  r_tri    = d_in[5];
    const void*  r_rel    = d_in[6];
    float* out = (float*)d_out;

    int N = in_sizes[0] / DMAX;
    int R = in_sizes[1] / DMAX;
    int depth = in_sizes[2] / DMAX;
    int T = in_sizes[3];
    if (N <= 0 || T <= 0) return;
    if (N > NMAX) N = NMAX;
    if (T > TMAX) T = TMAX;
    if (R > RMAX) R = RMAX;
    if (depth > DEPMAX) depth = DEPMAX;
    int outd = (depth + 1) * DMAX;

    int M = (T > N + 1) ? T : (N + 1);
    k_zero<<<(M + 255) / 256, 256>>>(adj, T, N);
    k_prep<<<(T + 255) / 256, 256>>>(r_tri, r_rel, r_val, adj, T, R);

    int nb = (N + SCAN_CHUNK - 1) / SCAN_CHUNK;   // <= 25 for NMAX
    k_scan1<<<nb, 256>>>(N);
    k_scan3<<<(N + 255) / 256, 256>>>(N, nb);

    k_place<<<(T + 255) / 256, 256>>>(adj, T);
    k_normalize<<<R, 256>>>(rel_emb, attnk, depth);
    k_expa<<<(depth * ESPAN + 255) / 256, 256>>>(R, depth);

    int wblocks = (int)(((size_t)N * 32 + 255) / 256);
    k_weights<<<wblocks, 256>>>(N, T, depth);
    k_tanh0<<<((size_t)N * 32 + 255) / 256, 256>>>(features, out, N, outd);

    for (int l = 0; l < depth; l++) {
        int inbuf_is_B = (l & 1);
        int write_next = (l < depth - 1) ? 1 : 0;
        k_layer<<<wblocks, 256>>>(out, (l + 1) * DMAX, outd, N, T, R, l, inbuf_is_B, write_next);
    }
}

// round 16
// speedup vs baseline: 1.2019x; 1.0303x over previous
#include <cuda_runtime.h>
#include <cuda_fp16.h>
#include <math.h>

#define DMAX   256
#define NMAX   50000
#define TMAX   400000
#define RMAX   1000
#define DEPMAX 2
#define ESPAN  (2 * RMAX + 1)   // expa table: index = idx, idx in [0, 2R]
#define SCAN_CHUNK 2048          // elements per scan block (256 thr * 8)

// ---------------- static device scratch (no allocation allowed) ----------------
__device__ __align__(16) __half g_xA[(size_t)NMAX * DMAX];    // 25.6 MB
__device__ __align__(16) __half g_xB[(size_t)NMAX * DMAX];    // 25.6 MB
__device__ __align__(16) __half g_nrel[(size_t)RMAX * DMAX];  // 512 KB
__device__ float g_attrel[DEPMAX * RMAX];
__device__ float g_expa[DEPMAX * ESPAN];       // exp(a - mg) per idx per layer
__device__ int   g_mgbits[DEPMAX];             // per-layer max|a| as float bits
__device__ float g_w[(size_t)DEPMAX * TMAX];   // per-edge softmax weights per layer
__device__ int   g_counts[NMAX + 1];
__device__ int   g_rowptr[NMAX + 1];
__device__ int   g_cursor[NMAX];
__device__ int   g_bsum[64];
__device__ unsigned g_meta[TMAX];   // CSR edge: src | (idx << 17); idx: 0=none, 1..R=+rel, R+1..2R=-rel
__device__ int   g_tricode[TMAX];   // per-triple idx before CSR permutation
__device__ int   g_flag64;          // 1 if index arrays are int64, 0 if int32

// ---------------- helpers ----------------
__device__ __forceinline__ long long ld_idx(const void* p, long long i) {
    return g_flag64 ? ((const long long*)p)[i] : (long long)((const int*)p)[i];
}

__device__ __forceinline__ float blockReduce256(float v, float* sm) {
    #pragma unroll
    for (int off = 16; off; off >>= 1) v += __shfl_xor_sync(0xffffffffu, v, off);
    int w = threadIdx.x >> 5;
    if ((threadIdx.x & 31) == 0) sm[w] = v;
    __syncthreads();
    if (threadIdx.x < 32) {
        float r = (threadIdx.x < 8) ? sm[threadIdx.x] : 0.0f;
        #pragma unroll
        for (int off = 4; off; off >>= 1) r += __shfl_xor_sync(0xffffffffu, r, off);
        if (threadIdx.x == 0) sm[0] = r;
    }
    __syncthreads();
    float res = sm[0];
    __syncthreads();
    return res;
}

// dot of 8 fp16 pairs held as raw uint4 (convert on the fly, f32 fma accumulate)
__device__ __forceinline__ float dot8h(const uint4& xr, const uint4& vr) {
    const __half2* hx = (const __half2*)&xr;
    const __half2* hv = (const __half2*)&vr;
    float p = 0.0f;
    #pragma unroll
    for (int i = 0; i < 4; i++) {
        float2 a = __half22float2(hx[i]);
        float2 b = __half22float2(hv[i]);
        p = fmaf(a.x, b.x, p);
        p = fmaf(a.y, b.y, p);
    }
    return p;
}

// acc += w * (x - t2 * v), operands raw fp16
__device__ __forceinline__ void axpy8h(float acc[8], float w, float t2,
                                       const uint4& xr, const uint4& vr) {
    const __half2* hx = (const __half2*)&xr;
    const __half2* hv = (const __half2*)&vr;
    #pragma unroll
    for (int i = 0; i < 4; i++) {
        float2 a = __half22float2(hx[i]);
        float2 b = __half22float2(hv[i]);
        acc[2 * i]     += w * (a.x - t2 * b.x);
        acc[2 * i + 1] += w * (a.y - t2 * b.y);
    }
}

// ---------------- kernels ----------------

// zero scratch; block 0 / warp 0 also detects int64 vs int32 index width
__global__ void k_zero(const void* adj, int T, int N) {
    int i = blockIdx.x * blockDim.x + threadIdx.x;
    if (blockIdx.x == 0 && threadIdx.x < 32) {
        int lane = threadIdx.x;
        int lim = (T < 32) ? T : 32;
        int bad = 0;
        if (lane < lim) {
            long long v = ((const long long*)adj)[lane];
            if (v < 0 || v >= (long long)N) bad = 1;
        }
        unsigned m = __ballot_sync(0xffffffffu, bad);
        if (lane == 0) g_flag64 = (m == 0u) ? 1 : 0;
    }
    if (i < DEPMAX) g_mgbits[i] = 0;
    if (i < T) g_tricode[i] = 0;
    if (i <= N) g_counts[i] = 0;
    if (i < N) g_cursor[i] = 0;
}

// fused: tri_rel idx scatter + dst histogram
// idx: 0 = zero tri_rel; [1,R] = +rel; [R+1,2R] = -rel
__global__ void k_prep(const void* r_tri, const void* r_rel,
                       const float* __restrict__ r_val, const void* adj, int T, int R) {
    int t = blockIdx.x * blockDim.x + threadIdx.x;
    if (t >= T) return;
    long long seg = ld_idx(r_tri, t);
    long long rel = ld_idx(r_rel, t);
    float v = r_val[t];
    int idx = 0;
    if (v > 0.0f)      idx = (int)rel + 1;
    else if (v < 0.0f) idx = R + (int)rel + 1;
    if (seg >= 0 && seg < T) g_tricode[seg] = idx;
    long long dst = ld_idx(adj, t);
    atomicAdd(&g_counts[(int)dst], 1);
}

// ---- scan phase 1: per-chunk local exclusive prefix + chunk totals ----
__global__ void k_scan1(int N) {
    __shared__ int warpsum[8];
    int tid = threadIdx.x;
    int base = blockIdx.x * SCAN_CHUNK + tid * 8;
    int v[8];
    #pragma unroll
    for (int i = 0; i < 8; i++) {
        int j = base + i;
        v[i] = (j < N) ? g_counts[j] : 0;
    }
    int pref[8];
    int s = 0;
    #pragma unroll
    for (int i = 0; i < 8; i++) { pref[i] = s; s += v[i]; }
    int lane = tid & 31, w = tid >> 5;
    int inc = s;
    #pragma unroll
    for (int off = 1; off < 32; off <<= 1) {
        int t = __shfl_up_sync(0xffffffffu, inc, off);
        if (lane >= off) inc += t;
    }
    if (lane == 31) warpsum[w] = inc;
    __syncthreads();
    int woff = 0;
    #pragma unroll
    for (int k = 0; k < 7; k++) if (k < w) woff += warpsum[k];
    int toff = woff + inc - s;
    #pragma unroll
    for (int i = 0; i < 8; i++) {
        int j = base + i;
        if (j < N) g_rowptr[j] = toff + pref[i];
    }
    if (tid == 255) g_bsum[blockIdx.x] = woff + inc;
}

// ---- scan phase 2 (fused): add chunk-exclusive offsets ----
__global__ void k_scan3(int N, int nb) {
    __shared__ int s_off;
    int chunk = (blockIdx.x << 8) / SCAN_CHUNK;
    if (threadIdx.x < 32) {
        int b = threadIdx.x;
        int v = (b < nb) ? g_bsum[b] : 0;
        int contrib = (b < chunk) ? v : 0;
        #pragma unroll
        for (int off = 16; off; off >>= 1) contrib += __shfl_xor_sync(0xffffffffu, contrib, off);
        if (b == 0) s_off = contrib;
        if (blockIdx.x == 0) {
            int tot = v;
            #pragma unroll
            for (int off = 16; off; off >>= 1) tot += __shfl_xor_sync(0xffffffffu, tot, off);
            if (b == 0) g_rowptr[N] = tot;
        }
    }
    __syncthreads();
    int j = blockIdx.x * 256 + threadIdx.x;
    if (j < N) g_rowptr[j] += s_off;
}

// single packed scattered store per edge
__global__ void k_place(const void* adj, int T) {
    int t = blockIdx.x * blockDim.x + threadIdx.x;
    if (t >= T) return;
    int dst = (int)ld_idx(adj, t);
    int src = (int)ld_idx(adj, (long long)T + t);
    int pos = g_rowptr[dst] + atomicAdd(&g_cursor[dst], 1);
    g_meta[pos] = (unsigned)src | ((unsigned)g_tricode[t] << 17);
}

// L2-normalize rel_emb rows (f32 math, fp16 store); logits + per-layer max|a|.
__global__ void k_normalize(const float* __restrict__ rel_emb,
                            const float* __restrict__ attnk, int depth) {
    __shared__ float sm[32];
    int r = blockIdx.x;
    int d = threadIdx.x;
    float v = rel_emb[(size_t)r * DMAX + d];
    float ss = blockReduce256(v * v, sm);
    float scale = 1.0f / fmaxf(sqrtf(ss), 1e-12f);
    float nv = v * scale;
    g_nrel[(size_t)r * DMAX + d] = __float2half_rn(nv);
    for (int l = 0; l < depth; l++) {
        float a = blockReduce256(nv * attnk[(size_t)l * DMAX + d], sm);
        if (d == 0) {
            g_attrel[l * RMAX + r] = a;
            atomicMax(&g_mgbits[l], __float_as_int(fabsf(a)));  // |a| >= 0: int cmp ok
        }
    }
}

// tabulate exp(a(idx) - mg) for idx in [0, 2R]
__global__ void k_expa(int R, int depth) {
    int i = blockIdx.x * blockDim.x + threadIdx.x;
    if (i >= depth * ESPAN) return;
    int l = i / ESPAN, j = i % ESPAN;
    float a = 0.0f;
    if (j >= 1 && j <= R)              a =  g_attrel[l * RMAX + (j - 1)];
    else if (j > R && j <= 2 * R)      a = -g_attrel[l * RMAX + (j - R - 1)];
    else if (j != 0)                   { g_expa[l * ESPAN + j] = 0.0f; return; }
    float mg = __int_as_float(g_mgbits[l]);
    g_expa[l * ESPAN + j] = expf(a - mg);
}

// Per-edge softmax weights for ALL layers: one sum pass + one write pass.
__global__ void __launch_bounds__(256) k_weights(int N, int T, int depth) {
    int gw   = (blockIdx.x * blockDim.x + threadIdx.x) >> 5;
    int lane = threadIdx.x & 31;
    if (gw >= N) return;
    int e0 = g_rowptr[gw], e1 = g_rowptr[gw + 1];
    if (e0 >= e1) return;

    float s0 = 0.0f, s1 = 0.0f;
    for (int e = e0 + lane; e < e1; e += 32) {
        unsigned j = g_meta[e] >> 17;
        s0 += g_expa[j];
        if (depth > 1) s1 += g_expa[ESPAN + j];
    }
    #pragma unroll
    for (int off = 16; off; off >>= 1) {
        s0 += __shfl_xor_sync(0xffffffffu, s0, off);
        s1 += __shfl_xor_sync(0xffffffffu, s1, off);
    }
    float i0 = 1.0f / s0;
    float i1 = (depth > 1) ? 1.0f / s1 : 0.0f;
    for (int e = e0 + lane; e < e1; e += 32) {
        unsigned j = g_meta[e] >> 17;
        g_w[e] = g_expa[j] * i0;
        if (depth > 1) g_w[(size_t)T + e] = g_expa[ESPAN + j] * i1;
    }
}

// x0 = tanh(features); fp16 to ping buffer, exact f32 to output slice 0.
// out stores use streaming hint (write-once) to protect L2 for the x buffers.
__global__ void k_tanh0(const float* __restrict__ f, float* __restrict__ out,
                        int N, int outd) {
    int i = blockIdx.x * blockDim.x + threadIdx.x;   // over N*32 groups of 8
    if (i >= N * 32) return;
    int row = i >> 5, grp = i & 31;
    const float4* src = (const float4*)(f + (size_t)row * DMAX) + grp * 2;
    float4 a = src[0], b = src[1];
    a.x = tanhf(a.x); a.y = tanhf(a.y); a.z = tanhf(a.z); a.w = tanhf(a.w);
    b.x = tanhf(b.x); b.y = tanhf(b.y); b.z = tanhf(b.z); b.w = tanhf(b.w);
    float4* ow = (float4*)(out + (size_t)row * outd) + grp * 2;
    __stcs(ow,     a);
    __stcs(ow + 1, b);
    float4 hraw;
    __half2* hh = (__half2*)&hraw;
    hh[0] = __floats2half2_rn(a.x, a.y);
    hh[1] = __floats2half2_rn(a.z, a.w);
    hh[2] = __floats2half2_rn(b.x, b.y);
    hh[3] = __floats2half2_rn(b.z, b.w);
    ((float4*)(g_xA + (size_t)row * DMAX))[grp] = hraw;
}

// One warp per destination node: reflected weighted aggregation (weights precomputed).
// 2-way unroll, packed fp16 operands. Cache policy: x gathers bypass L1 (__ldcg —
// no per-SM reuse, keeps L1 free for g_nrel), v gathers default (L1-resident table),
// final out stores streaming (__stcs — write-once, protect L2 for x buffers).
__global__ void __launch_bounds__(256)
k_layer(float* __restrict__ out, int outoff, int outd, int N, int T, int R, int l,
        int inbuf_is_B, int write_next) {
    int gw   = (blockIdx.x * blockDim.x + threadIdx.x) >> 5;
    int lane = threadIdx.x & 31;
    if (gw >= N) return;
    const __half* __restrict__ xin = inbuf_is_B ? g_xB : g_xA;
    __half*       __restrict__ xnx = inbuf_is_B ? g_xA : g_xB;
    const float*  __restrict__ wrow = g_w + (size_t)l * T;

    int e0 = g_rowptr[gw], e1 = g_rowptr[gw + 1];
    float acc[8] = {0, 0, 0, 0, 0, 0, 0, 0};

    int e = e0;
    // 2-way unrolled: overlap the two SHFL dot-reduction chains
    for (; e + 1 < e1; e += 2) {
        unsigned m0 = g_meta[e], m1 = g_meta[e + 1];
        float w0 = wrow[e], w1 = wrow[e + 1];
        unsigned s0 = m0 & 0x1FFFFu, s1 = m1 & 0x1FFFFu;
        unsigned i0 = m0 >> 17,      i1 = m1 >> 17;
        int r0 = (i0 > (unsigned)R) ? (int)(i0 - R - 1) : (int)i0 - 1;  // -1 if i0==0
        int r1 = (i1 > (unsigned)R) ? (int)(i1 - R - 1) : (int)i1 - 1;
        uint4 x0 = __ldcg(((const uint4*)(xin + (size_t)s0 * DMAX)) + lane);
        uint4 x1 = __ldcg(((const uint4*)(xin + (size_t)s1 * DMAX)) + lane);
        uint4 v0 = ((const uint4*)(g_nrel + (size_t)(r0 < 0 ? 0 : r0) * DMAX))[lane];
        uint4 v1 = ((const uint4*)(g_nrel + (size_t)(r1 < 0 ? 0 : r1) * DMAX))[lane];
        float p0 = dot8h(x0, v0);
        float p1 = dot8h(x1, v1);
        #pragma unroll
        for (int off = 16; off; off >>= 1) {
            p0 += __shfl_xor_sync(0xffffffffu, p0, off);
            p1 += __shfl_xor_sync(0xffffffffu, p1, off);
        }
        float t20 = (r0 >= 0) ? 2.0f * p0 : 0.0f;
        float t21 = (r1 >= 0) ? 2.0f * p1 : 0.0f;
        axpy8h(acc, w0, t20, x0, v0);
        axpy8h(acc, w1, t21, x1, v1);
    }
    for (; e < e1; e++) {
        unsigned m = g_meta[e];
        float w = wrow[e];
        unsigned sr = m & 0x1FFFFu;
        unsigned ix = m >> 17;
        int r = (ix > (unsigned)R) ? (int)(ix - R - 1) : (int)ix - 1;
        uint4 x = __ldcg(((const uint4*)(xin + (size_t)sr * DMAX)) + lane);
        uint4 v = ((const uint4*)(g_nrel + (size_t)(r < 0 ? 0 : r) * DMAX))[lane];
        float p = dot8h(x, v);
        #pragma unroll
        for (int off = 16; off; off >>= 1) p += __shfl_xor_sync(0xffffffffu, p, off);
        float t2 = (r >= 0) ? 2.0f * p : 0.0f;
        axpy8h(acc, w, t2, x, v);
    }

    float o[8];
    #pragma unroll
    for (int i = 0; i < 8; i++) o[i] = tanhf(acc[i]);

    if (write_next) {
        float4 hraw;
        __half2* hh = (__half2*)&hraw;
        hh[0] = __floats2half2_rn(o[0], o[1]);
        hh[1] = __floats2half2_rn(o[2], o[3]);
        hh[2] = __floats2half2_rn(o[4], o[5]);
        hh[3] = __floats2half2_rn(o[6], o[7]);
        ((float4*)(xnx + (size_t)gw * DMAX))[lane] = hraw;
    }
    float4* ow = (float4*)(out + (size_t)gw * outd + outoff);
    __stcs(ow + 2 * lane,     make_float4(o[0], o[1], o[2], o[3]));
    __stcs(ow + 2 * lane + 1, make_float4(o[4], o[5], o[6], o[7]));
}

// ---------------- launch ----------------
extern "C" void kernel_launch(void* const* d_in, const int* in_sizes, int n_in,
                              void* d_out, int out_size) {
    const float* features = (const float*)d_in[0];
    const float* rel_emb  = (const float*)d_in[1];
    const float* attnk    = (const float*)d_in[2];
    const float* r_val    = (const float*)d_in[3];
    const void*  adj      = d_in[4];
    const void*  r_tri    = d_in[5];
    const void*  r_rel    = d_in[6];
    float* out = (float*)d_out;

    int N = in_sizes[0] / DMAX;
    int R = in_sizes[1] / DMAX;
    int depth = in_sizes[2] / DMAX;
    int T = in_sizes[3];
    if (N <= 0 || T <= 0) return;
    if (N > NMAX) N = NMAX;
    if (T > TMAX) T = TMAX;
    if (R > RMAX) R = RMAX;
    if (depth > DEPMAX) depth = DEPMAX;
    int outd = (depth + 1) * DMAX;

    int M = (T > N + 1) ? T : (N + 1);
    k_zero<<<(M + 255) / 256, 256>>>(adj, T, N);
    k_prep<<<(T + 255) / 256, 256>>>(r_tri, r_rel, r_val, adj, T, R);

    int nb = (N + SCAN_CHUNK - 1) / SCAN_CHUNK;   // <= 25 for NMAX
    k_scan1<<<nb, 256>>>(N);
    k_scan3<<<(N + 255) / 256, 256>>>(N, nb);

    k_place<<<(T + 255) / 256, 256>>>(adj, T);
    k_normalize<<<R, 256>>>(rel_emb, attnk, depth);
    k_expa<<<(depth * ESPAN + 255) / 256, 256>>>(R, depth);

    int wblocks = (int)(((size_t)N * 32 + 255) / 256);
    k_weights<<<wblocks, 256>>>(N, T, depth);
    k_tanh0<<<((size_t)N * 32 + 255) / 256, 256>>>(features, out, N, outd);

    for (int l = 0; l < depth; l++) {
        int inbuf_is_B = (l & 1);
        int write_next = (l < depth - 1) ? 1 : 0;
        k_layer<<<wblocks, 256>>>(out, (l + 1) * DMAX, outd, N, T, R, l, inbuf_is_B, write_next);
    }
}